// round 2
// baseline (speedup 1.0000x reference)
#include <cuda_runtime.h>

#define N    512
#define NA   180
#define NCH  4
#define YPC  (N / NCH)   // 128 y-samples per chunk

// Scratch (no allocations allowed): transposed image + per-chunk partials.
__device__ float g_imgT[N * N];
__device__ float g_partial[NCH * N * NA];

// ---------------------------------------------------------------------------
// Tiled transpose: img -> g_imgT  (1 MB, runs once per launch, ~negligible)
// ---------------------------------------------------------------------------
__global__ void transpose_k(const float* __restrict__ img) {
    __shared__ float tile[32][33];
    int x  = blockIdx.x * 32 + threadIdx.x;
    int y0 = blockIdx.y * 32;
#pragma unroll
    for (int j = threadIdx.y; j < 32; j += 8)
        tile[j][threadIdx.x] = img[(y0 + j) * N + x];
    __syncthreads();
    int xo  = blockIdx.y * 32 + threadIdx.x;
    int yo0 = blockIdx.x * 32;
#pragma unroll
    for (int j = threadIdx.y; j < 32; j += 8)
        g_imgT[(yo0 + j) * N + xo] = tile[threadIdx.x][j];
}

// ---------------------------------------------------------------------------
// Radon: one thread = one (detector d, angle a) pair, partial sum over a
// y-chunk. Per-angle we sample either img or imgT (coords swapped) so that
// the warp-lane (detector) axis has the SMALLER row derivative:
//   img :  row = sy (drow/dd = -sin),  col = sx (dcol/dd = cos)
//   imgT:  row = sx (drow/dd =  cos),  col = sy (dcol/dd = -sin)
// -> rows spanned per warp ~ 31*min(|sin|,|cos|), cols contiguous-ish.
// ---------------------------------------------------------------------------
__global__ void __launch_bounds__(128) radon_k(const float* __restrict__ img,
                                               const int*   __restrict__ angles) {
    const int d  = blockIdx.x * blockDim.x + threadIdx.x;  // detector 0..511
    const int a  = blockIdx.y;                             // angle index
    const int ch = blockIdx.z;                             // y-chunk

    const float c = (N - 1) * 0.5f;
    const float t = (float)angles[a] * 0.017453292519943295f;
    float si, co;
    sincosf(t, &si, &co);

    const bool useT = fabsf(si) > fabsf(co);
    const float* __restrict__ src = useT ? g_imgT : img;

    const float xc = (float)d - c;
    // row = dr*yc + rbase ; col = dc*yc + cbase
    float dr, rbase, dc, cbase;
    if (useT) { dr = si; rbase = fmaf( co, xc, c);
                dc = co; cbase = fmaf(-si, xc, c); }
    else      { dr = co; rbase = fmaf(-si, xc, c);
                dc = si; cbase = fmaf( co, xc, c); }

    float acc = 0.0f;
    const int ybeg = ch * YPC;
#pragma unroll 4
    for (int y = ybeg; y < ybeg + YPC; ++y) {
        const float yc  = (float)y - c;
        const float row = fmaf(dr, yc, rbase);
        const float col = fmaf(dc, yc, cbase);

        const float rf = floorf(row), cf = floorf(col);
        const float wr = row - rf,    wc = col - cf;
        const int   ir = (int)rf,     ic = (int)cf;

        float v00, v01, v10, v11;
        if ((unsigned)ir < (unsigned)(N - 1) && (unsigned)ic < (unsigned)(N - 1)) {
            // interior fast path: 4 unchecked loads
            const float* p = src + ir * N + ic;
            v00 = __ldg(p);     v01 = __ldg(p + 1);
            v10 = __ldg(p + N); v11 = __ldg(p + N + 1);
        } else {
            // boundary / outside: per-corner valid-else-zero (matches reference)
            const bool r0 = (unsigned)ir       < (unsigned)N;
            const bool r1 = (unsigned)(ir + 1) < (unsigned)N;
            const bool c0 = (unsigned)ic       < (unsigned)N;
            const bool c1 = (unsigned)(ic + 1) < (unsigned)N;
            v00 = (r0 && c0) ? src[ir * N + ic]           : 0.0f;
            v01 = (r0 && c1) ? src[ir * N + ic + 1]       : 0.0f;
            v10 = (r1 && c0) ? src[(ir + 1) * N + ic]     : 0.0f;
            v11 = (r1 && c1) ? src[(ir + 1) * N + ic + 1] : 0.0f;
        }
        const float top = fmaf(wc, v01 - v00, v00);
        const float bot = fmaf(wc, v11 - v10, v10);
        acc += fmaf(wr, bot - top, top);
    }
    g_partial[(ch * N + d) * NA + a] = acc;
}

// ---------------------------------------------------------------------------
// Deterministic partial reduction: out[i] = sum over chunks (fixed order).
// ---------------------------------------------------------------------------
__global__ void reduce_k(float* __restrict__ out) {
    const int i = blockIdx.x * blockDim.x + threadIdx.x;
    if (i < N * NA) {
        float s = 0.0f;
#pragma unroll
        for (int ch = 0; ch < NCH; ++ch)
            s += g_partial[ch * (N * NA) + i];
        out[i] = s;
    }
}

extern "C" void kernel_launch(void* const* d_in, const int* in_sizes, int n_in,
                              void* d_out, int out_size) {
    const float* img    = (const float*)d_in[0];
    const int*   angles = (const int*)d_in[1];
    float*       out    = (float*)d_out;

    transpose_k<<<dim3(N / 32, N / 32), dim3(32, 8)>>>(img);
    radon_k<<<dim3(N / 128, NA, NCH), 128>>>(img, angles);
    reduce_k<<<(N * NA + 255) / 256, 256>>>(out);
}